// round 12
// baseline (speedup 1.0000x reference)
#include <cuda_runtime.h>
#include <cuda_bf16.h>
#include <math.h>
#include <stdint.h>

typedef __nv_bfloat16  bf16;
typedef __nv_bfloat162 bf162;

#define Bn_TOK   100352      // 8*4*56*56 = 1024 windows * 98
#define NWIN     1024
#define SCALE_Q  0.17677669529663687f   // 32^-0.5
#define LN_EPS   1e-5f

// ---------------------------------------------------------------------------
// Scratch
// ---------------------------------------------------------------------------
__device__ bf16  g_qkv [(long long)Bn_TOK * 384];
__device__ bf16  g_att [(long long)Bn_TOK * 128];
__device__ float g_x1  [(long long)Bn_TOK * 128];
__device__ bf16  g_wqkv[128 * 384];
__device__ bf16  g_wproj[128 * 128];
__device__ bf16  g_wfc1[128 * 512];
__device__ bf16  g_wfc2[512 * 128];

// ---------------------------------------------------------------------------
__global__ void f2bf_kernel(const float* __restrict__ s, bf16* __restrict__ d, int n)
{
    int i = blockIdx.x * 256 + threadIdx.x;
    if (i < n) d[i] = __float2bfloat16(s[i]);
}

__device__ __forceinline__ int map_winrow_to_token(int row)
{
    int win = row / 98, n = row - win * 98;
    int b    = win >> 7;
    int winS = win & 127;
    int wd = winS >> 6, wh = (winS >> 3) & 7, ww = winS & 7;
    int td = n / 49, rem = n - td * 49, th = rem / 7, tw = rem - th * 7;
    int d = wd * 2 + td;
    int h = wh * 7 + th;
    int w = ww * 7 + tw;
    int ds = (d + 1) & 3;
    int hs = h + 3; if (hs >= 56) hs -= 56;
    int ws = w + 3; if (ws >= 56) ws -= 56;
    return ((b * 4 + ds) * 56 + hs) * 56 + ws;
}

// ---------------------------------------------------------------------------
// MMA primitives
// ---------------------------------------------------------------------------
__device__ __forceinline__ void cp16(void* dst, const void* src)
{
    uint32_t d = (uint32_t)__cvta_generic_to_shared(dst);
    asm volatile("cp.async.ca.shared.global [%0], [%1], 16;\n" :: "r"(d), "l"(src));
}
__device__ __forceinline__ void ldm_x4(uint32_t& r0, uint32_t& r1, uint32_t& r2,
                                       uint32_t& r3, const bf16* p)
{
    uint32_t a = (uint32_t)__cvta_generic_to_shared(p);
    asm volatile("ldmatrix.sync.aligned.m8n8.x4.shared.b16 {%0,%1,%2,%3}, [%4];\n"
                 : "=r"(r0), "=r"(r1), "=r"(r2), "=r"(r3) : "r"(a));
}
__device__ __forceinline__ void ldm_x4_t(uint32_t& r0, uint32_t& r1, uint32_t& r2,
                                         uint32_t& r3, const bf16* p)
{
    uint32_t a = (uint32_t)__cvta_generic_to_shared(p);
    asm volatile("ldmatrix.sync.aligned.m8n8.x4.trans.shared.b16 {%0,%1,%2,%3}, [%4];\n"
                 : "=r"(r0), "=r"(r1), "=r"(r2), "=r"(r3) : "r"(a));
}
__device__ __forceinline__ void mma_bf16(float c[4], const uint32_t a[4], const uint32_t b[2])
{
    asm volatile(
        "mma.sync.aligned.m16n8k16.row.col.f32.bf16.bf16.f32 "
        "{%0,%1,%2,%3}, {%4,%5,%6,%7}, {%8,%9}, {%0,%1,%2,%3};\n"
        : "+f"(c[0]), "+f"(c[1]), "+f"(c[2]), "+f"(c[3])
        : "r"(a[0]), "r"(a[1]), "r"(a[2]), "r"(a[3]), "r"(b[0]), "r"(b[1]));
}

// ---------------------------------------------------------------------------
// Tensor-core windowed attention (unchanged from R11 passing kernel)
// ---------------------------------------------------------------------------
#define ATT2_SMEM 61376

__global__ void __launch_bounds__(256)
attn2_kernel(const bf16* __restrict__ qkv,
             const float* __restrict__ rpb,
             bf16* __restrict__ out)
{
    extern __shared__ char smc[];
    bf16*  q_s   = (bf16*)(smc);
    bf16*  k_s   = (bf16*)(smc + 10240);
    bf16*  v_s   = (bf16*)(smc + 19200);
    bf16*  P     = (bf16*)(smc + 28160);
    float* rpb_s = (float*)(smc + 58880);
    int*   jd    = (int*)  (smc + 60908);

    int blk  = blockIdx.x;
    int win  = blk >> 2;
    int head = blk & 3;
    int tid  = threadIdx.x;
    int w    = tid >> 5, lane = tid & 31;
    int g    = lane >> 2, tg = lane & 3;
    int t1   = (lane >> 3) & 1;
    int t2   = lane >> 4;
    int rr   = lane & 7;
    int m0   = w * 16;

    int winS = win & 127;
    int wd = winS >> 6, wh = (winS >> 3) & 7, ww = winS & 7;
    if (tid < 112) {
        int v = 0;
        if (tid < 98) {
            int td = tid / 49, rem = tid - td * 49, th = rem / 7, tw = rem - th * 7;
            int d = wd * 2 + td, h = wh * 7 + th, wq = ww * 7 + tw;
            int dr = d < 2 ? 0 : (d < 3 ? 1 : 2);
            int hr = h < 49 ? 0 : (h < 53 ? 1 : 2);
            int wr = wq < 49 ? 0 : (wq < 53 ? 1 : 2);
            v = td | (th << 4) | (tw << 8) | ((dr * 9 + hr * 3 + wr) << 12);
        }
        jd[tid] = v;
    }
    for (int i = tid; i < 507; i += 256) rpb_s[i] = rpb[i * 4 + head];

    const bf16* base = qkv + (long long)win * 98 * 384 + head * 32;
    for (int idx = tid; idx < 98 * 4; idx += 256) {
        int row = idx >> 2, ch = idx & 3;
        const int4* src = (const int4*)(base + row * 384 + ch * 8);
        *(int4*)(q_s + row * 40 + ch * 8) = src[0];
        *(int4*)(k_s + row * 40 + ch * 8) = src[16];
        *(int4*)(v_s + row * 40 + ch * 8) = src[32];
    }
    int4 zz = make_int4(0, 0, 0, 0);
    for (int idx = tid; idx < 14 * 5; idx += 256) {
        int row = 98 + idx / 5, ch = idx % 5;
        *(int4*)(k_s + row * 40 + ch * 8) = zz;
        *(int4*)(v_s + row * 40 + ch * 8) = zz;
    }
    __syncthreads();

    float c[14][4];
    #pragma unroll
    for (int nt = 0; nt < 14; nt++)
        #pragma unroll
        for (int e = 0; e < 4; e++) c[nt][e] = 0.f;

    #pragma unroll
    for (int kh = 0; kh < 2; kh++) {
        int kb = kh * 16;
        uint32_t a[4];
        ldm_x4(a[0], a[1], a[2], a[3], q_s + (m0 + t1 * 8 + rr) * 40 + kb + t2 * 8);
        #pragma unroll
        for (int np = 0; np < 7; np++) {
            uint32_t r0, r1, r2, r3;
            ldm_x4(r0, r1, r2, r3, k_s + (np * 16 + t1 * 8 + rr) * 40 + kb + t2 * 8);
            uint32_t b0[2] = {r0, r2};
            uint32_t b1[2] = {r1, r3};
            mma_bf16(c[np * 2],     a, b0);
            mma_bf16(c[np * 2 + 1], a, b1);
        }
    }

    #pragma unroll
    for (int half = 0; half < 2; half++) {
        int  i     = m0 + g + half * 8;
        bool valid = (i < 98);
        int  pi    = jd[valid ? i : 0];
        int  di = pi & 15, hi = (pi >> 4) & 15, wi = (pi >> 8) & 15, li = pi >> 12;

        float mx = -1e30f;
        #pragma unroll
        for (int nt = 0; nt < 14; nt++) {
            #pragma unroll
            for (int e = 0; e < 2; e++) {
                int j = nt * 8 + tg * 2 + e;
                float v = -1e30f;
                if (valid && j < 98) {
                    int pj = jd[j];
                    int dj = pj & 15, hj = (pj >> 4) & 15, wj = (pj >> 8) & 15;
                    int rel = (di - dj + 1) * 169 + (hi - hj + 6) * 13 + (wi - wj + 6);
                    float msk = (li == (pj >> 12)) ? 0.f : -100.f;
                    v = c[nt][half * 2 + e] * SCALE_Q + rpb_s[rel] + msk;
                }
                c[nt][half * 2 + e] = v;
                mx = fmaxf(mx, v);
            }
        }
        mx = fmaxf(mx, __shfl_xor_sync(0xffffffffu, mx, 1));
        mx = fmaxf(mx, __shfl_xor_sync(0xffffffffu, mx, 2));
        float sum = 0.f;
        #pragma unroll
        for (int nt = 0; nt < 14; nt++) {
            #pragma unroll
            for (int e = 0; e < 2; e++) {
                float ev = __expf(c[nt][half * 2 + e] - mx);
                c[nt][half * 2 + e] = ev;
                sum += ev;
            }
        }
        sum += __shfl_xor_sync(0xffffffffu, sum, 1);
        sum += __shfl_xor_sync(0xffffffffu, sum, 2);
        float inv = 1.f / sum;
        #pragma unroll
        for (int nt = 0; nt < 14; nt++) {
            float p0 = valid ? c[nt][half * 2]     * inv : 0.f;
            float p1 = valid ? c[nt][half * 2 + 1] * inv : 0.f;
            *(bf162*)(P + i * 120 + nt * 8 + tg * 2) = __floats2bfloat162_rn(p0, p1);
        }
    }
    __syncthreads();

    float c2[4][4];
    #pragma unroll
    for (int nt = 0; nt < 4; nt++)
        #pragma unroll
        for (int e = 0; e < 4; e++) c2[nt][e] = 0.f;

    #pragma unroll
    for (int kh = 0; kh < 7; kh++) {
        int kb = kh * 16;
        uint32_t a[4];
        ldm_x4(a[0], a[1], a[2], a[3], P + (m0 + t1 * 8 + rr) * 120 + kb + t2 * 8);
        #pragma unroll
        for (int ch = 0; ch < 2; ch++) {
            uint32_t r0, r1, r2, r3;
            ldm_x4_t(r0, r1, r2, r3, v_s + (kb + t1 * 8 + rr) * 40 + ch * 16 + t2 * 8);
            uint32_t b0[2] = {r0, r1};
            uint32_t b1[2] = {r2, r3};
            mma_bf16(c2[ch * 2],     a, b0);
            mma_bf16(c2[ch * 2 + 1], a, b1);
        }
    }

    bf16* obase = out + (long long)win * 98 * 128 + head * 32;
    #pragma unroll
    for (int half = 0; half < 2; half++) {
        int i = m0 + g + half * 8;
        if (i < 98) {
            #pragma unroll
            for (int nt = 0; nt < 4; nt++) {
                int col = nt * 8 + tg * 2;
                *(bf162*)(obase + (long long)i * 128 + col) =
                    __floats2bfloat162_rn(c2[nt][half * 2], c2[nt][half * 2 + 1]);
            }
        }
    }
}

// ---------------------------------------------------------------------------
// Single-shot K=128 GEMM with optional fused LayerNorm prologue.
// LNMODE 0: A is bf16 [M][128]
// LNMODE 1: A is fp32 x; rows gathered via map_winrow_to_token + LayerNorm
// EPI 0: store (OUTBF)    EPI 1: scatter + residual (fp32, N must be 128)
// ---------------------------------------------------------------------------
#define TS 136
#define K128_SMEM (2 * 128 * TS * 2)   // 69632 B

template<int LNMODE, int ACT, int EPI, int OUTBF>
__global__ void __launch_bounds__(256, 2)
gemm_k128(const void* __restrict__ Av, const bf16* __restrict__ B,
          const float* __restrict__ bias, void* __restrict__ Cv,
          const float* __restrict__ res,
          const float* __restrict__ gam, const float* __restrict__ bet, int N)
{
    extern __shared__ bf16 gsm[];
    bf16* As = gsm;
    bf16* Bs = gsm + 128 * TS;

    int tid = threadIdx.x;
    int m0 = blockIdx.y * 128;
    int n0 = blockIdx.x * 128;
    int w    = tid >> 5, lane = tid & 31;
    int g    = lane >> 2, tg = lane & 3;
    int wm   = (w & 1) * 64;
    int wn   = (w >> 1) * 32;
    int t1   = (lane >> 3) & 1;
    int t2   = (lane >> 4);
    int rr   = lane & 7;

    // B tile: 128 rows x 128 cols
    #pragma unroll
    for (int r = 0; r < 8; r++) {
        int q = tid + r * 256;
        int row = q >> 4, ccc = q & 15;
        cp16(Bs + row * TS + ccc * 8, B + (long long)row * N + n0 + ccc * 8);
    }
    if (LNMODE == 0) {
        const bf16* Ab = (const bf16*)Av;
        #pragma unroll
        for (int r = 0; r < 8; r++) {
            int q = tid + r * 256;
            int row = q >> 4, ccc = q & 15;
            cp16(As + row * TS + ccc * 8, Ab + (long long)(m0 + row) * 128 + ccc * 8);
        }
    }
    asm volatile("cp.async.commit_group;\n");

    if (LNMODE == 1) {
        const float* Af = (const float*)Av;
        float4 gv = ((const float4*)gam)[lane];
        float4 bv = ((const float4*)bet)[lane];
        #pragma unroll 4
        for (int i = 0; i < 16; i++) {
            int row = w * 16 + i;
            int src = map_winrow_to_token(m0 + row);
            float4 v = ((const float4*)(Af + (long long)src * 128))[lane];
            float s  = v.x + v.y + v.z + v.w;
            float s2 = v.x * v.x + v.y * v.y + v.z * v.z + v.w * v.w;
            #pragma unroll
            for (int o = 16; o; o >>= 1) {
                s  += __shfl_xor_sync(0xffffffffu, s,  o);
                s2 += __shfl_xor_sync(0xffffffffu, s2, o);
            }
            float mu = s * (1.f / 128.f);
            float rs = rsqrtf(s2 * (1.f / 128.f) - mu * mu + LN_EPS);
            bf162* po = (bf162*)(As + row * TS + lane * 4);
            po[0] = __floats2bfloat162_rn((v.x - mu) * rs * gv.x + bv.x,
                                          (v.y - mu) * rs * gv.y + bv.y);
            po[1] = __floats2bfloat162_rn((v.z - mu) * rs * gv.z + bv.z,
                                          (v.w - mu) * rs * gv.w + bv.w);
        }
    }
    asm volatile("cp.async.wait_group 0;\n");
    __syncthreads();

    float c[4][4][4];
    #pragma unroll
    for (int mf = 0; mf < 4; mf++)
        #pragma unroll
        for (int nf = 0; nf < 4; nf++)
            #pragma unroll
            for (int r = 0; r < 4; r++) c[mf][nf][r] = 0.f;

    #pragma unroll
    for (int ks = 0; ks < 8; ks++) {
        int kb = ks * 16;
        uint32_t a[4][4], b[4][2];
        #pragma unroll
        for (int mf = 0; mf < 4; mf++)
            ldm_x4(a[mf][0], a[mf][1], a[mf][2], a[mf][3],
                   As + (wm + mf * 16 + t1 * 8 + rr) * TS + kb + t2 * 8);
        #pragma unroll
        for (int nh = 0; nh < 2; nh++) {
            uint32_t r0, r1, r2, r3;
            ldm_x4_t(r0, r1, r2, r3,
                     Bs + (kb + t1 * 8 + rr) * TS + wn + nh * 16 + t2 * 8);
            b[nh * 2][0] = r0; b[nh * 2][1] = r1;
            b[nh * 2 + 1][0] = r2; b[nh * 2 + 1][1] = r3;
        }
        #pragma unroll
        for (int mf = 0; mf < 4; mf++)
            #pragma unroll
            for (int nf = 0; nf < 4; nf++)
                mma_bf16(c[mf][nf], a[mf], b[nf]);
    }

    float* Cf = (float*)Cv;
    bf16*  Cb = (bf16*)Cv;
    #pragma unroll
    for (int mf = 0; mf < 4; mf++) {
        int r0 = m0 + wm + mf * 16 + g;
        int r1 = r0 + 8;
        long long d0 = r0, d1 = r1;
        if (EPI == 1) { d0 = map_winrow_to_token(r0); d1 = map_winrow_to_token(r1); }
        #pragma unroll
        for (int nf = 0; nf < 4; nf++) {
            int col = n0 + wn + nf * 8 + tg * 2;
            float b0 = bias[col], b1 = bias[col + 1];
            #pragma unroll
            for (int half = 0; half < 2; half++) {
                long long row = half ? r1 : r0;
                long long dst = half ? d1 : d0;
                float v0 = c[mf][nf][half * 2 + 0] + b0;
                float v1 = c[mf][nf][half * 2 + 1] + b1;
                if (ACT == 1) {
                    v0 = 0.5f * v0 * (1.f + erff(v0 * 0.70710678118654752f));
                    v1 = 0.5f * v1 * (1.f + erff(v1 * 0.70710678118654752f));
                }
                if (EPI == 1) {
                    float2 rv = *(const float2*)(res + dst * 128 + col);
                    *(float2*)(Cf + dst * 128 + col) = make_float2(rv.x + v0, rv.y + v1);
                } else if (OUTBF) {
                    *(bf162*)(Cb + row * N + col) = __floats2bfloat162_rn(v0, v1);
                } else {
                    *(float2*)(Cf + row * N + col) = make_float2(v0, v1);
                }
            }
        }
    }
}

// ---------------------------------------------------------------------------
// Fused MLP: out = x1 + fc2(gelu(fc1(LN(x1)))).  One block per 128 rows.
// smem: x1f[128][132] f32 | h2s[128][136] bf16 | hids[128][136] bf16 |
//       wb0[128][136] bf16 | wb1[128][136] bf16    total 206848 B
// ---------------------------------------------------------------------------
#define MLP_SMEM 206848

__global__ void __launch_bounds__(256, 1)
mlp_kernel(const float* __restrict__ x1, const bf16* __restrict__ wfc1,
           const float* __restrict__ b1, const bf16* __restrict__ wfc2,
           const float* __restrict__ b2,
           const float* __restrict__ gam, const float* __restrict__ bet,
           float* __restrict__ out)
{
    extern __shared__ char sm[];
    float* x1f  = (float*)sm;                    // 67584
    bf16*  h2s  = (bf16*)(sm + 67584);           // 34816
    bf16*  hids = (bf16*)(sm + 102400);          // 34816
    bf16*  wb0  = (bf16*)(sm + 137216);          // 34816
    bf16*  wb1  = (bf16*)(sm + 172032);          // 34816

    int tid = threadIdx.x;
    int m0 = blockIdx.x * 128;
    int w    = tid >> 5, lane = tid & 31;
    int g    = lane >> 2, tg = lane & 3;
    int wm   = (w & 1) * 64;
    int wn   = (w >> 1) * 32;
    int t1   = (lane >> 3) & 1;
    int t2   = (lane >> 4);
    int rr   = lane & 7;

    // preload weight chunk 0 of fc1 and fc2
    #pragma unroll
    for (int r = 0; r < 8; r++) {
        int q = tid + r * 256;
        int row = q >> 4, ccc = q & 15;
        cp16(wb0 + row * TS + ccc * 8, wfc1 + (long long)row * 512 + ccc * 8);
    }
    asm volatile("cp.async.commit_group;\n");
    #pragma unroll
    for (int r = 0; r < 8; r++) {
        int q = tid + r * 256;
        int row = q >> 4, ccc = q & 15;
        cp16(wb1 + row * TS + ccc * 8, wfc2 + (long long)row * 128 + ccc * 8);
    }
    asm volatile("cp.async.commit_group;\n");

    // LN2 prologue: also cache x1 tile (fp32) for the final residual
    {
        float4 gv = ((const float4*)gam)[lane];
        float4 bv = ((const float4*)bet)[lane];
        #pragma unroll 4
        for (int i = 0; i < 16; i++) {
            int row = w * 16 + i;
            float4 v = ((const float4*)(x1 + (long long)(m0 + row) * 128))[lane];
            ((float4*)(x1f + row * 132))[lane] = v;
            float s  = v.x + v.y + v.z + v.w;
            float s2 = v.x * v.x + v.y * v.y + v.z * v.z + v.w * v.w;
            #pragma unroll
            for (int o = 16; o; o >>= 1) {
                s  += __shfl_xor_sync(0xffffffffu, s,  o);
                s2 += __shfl_xor_sync(0xffffffffu, s2, o);
            }
            float mu = s * (1.f / 128.f);
            float rs = rsqrtf(s2 * (1.f / 128.f) - mu * mu + LN_EPS);
            bf162* po = (bf162*)(h2s + row * TS + lane * 4);
            po[0] = __floats2bfloat162_rn((v.x - mu) * rs * gv.x + bv.x,
                                          (v.y - mu) * rs * gv.y + bv.y);
            po[1] = __floats2bfloat162_rn((v.z - mu) * rs * gv.z + bv.z,
                                          (v.w - mu) * rs * gv.w + bv.w);
        }
    }

    float c2[4][4][4];
    #pragma unroll
    for (int mf = 0; mf < 4; mf++)
        #pragma unroll
        for (int nf = 0; nf < 4; nf++)
            #pragma unroll
            for (int r = 0; r < 4; r++) c2[mf][nf][r] = 0.f;

    #pragma unroll 1
    for (int cch = 0; cch < 4; cch++) {
        // -------- GEMM1: hid_c = h2s @ wfc1_c --------
        asm volatile("cp.async.wait_group 1;\n");
        __syncthreads();

        float c1[4][4][4];
        #pragma unroll
        for (int mf = 0; mf < 4; mf++)
            #pragma unroll
            for (int nf = 0; nf < 4; nf++)
                #pragma unroll
                for (int r = 0; r < 4; r++) c1[mf][nf][r] = 0.f;

        #pragma unroll
        for (int ks = 0; ks < 8; ks++) {
            int kb = ks * 16;
            uint32_t a[4][4], b[4][2];
            #pragma unroll
            for (int mf = 0; mf < 4; mf++)
                ldm_x4(a[mf][0], a[mf][1], a[mf][2], a[mf][3],
                       h2s + (wm + mf * 16 + t1 * 8 + rr) * TS + kb + t2 * 8);
            #pragma unroll
            for (int nh = 0; nh < 2; nh++) {
                uint32_t r0, r1, r2, r3;
                ldm_x4_t(r0, r1, r2, r3,
                         wb0 + (kb + t1 * 8 + rr) * TS + wn + nh * 16 + t2 * 8);
                b[nh * 2][0] = r0; b[nh * 2][1] = r1;
                b[nh * 2 + 1][0] = r2; b[nh * 2 + 1][1] = r3;
            }
            #pragma unroll
            for (int mf = 0; mf < 4; mf++)
                #pragma unroll
                for (int nf = 0; nf < 4; nf++)
                    mma_bf16(c1[mf][nf], a[mf], b[nf]);
        }

        // bias1 + GELU -> hids (bf16)
        #pragma unroll
        for (int mf = 0; mf < 4; mf++) {
            #pragma unroll
            for (int nf = 0; nf < 4; nf++) {
                int coll = wn + nf * 8 + tg * 2;
                int colg = cch * 128 + coll;
                float bb0 = b1[colg], bb1 = b1[colg + 1];
                #pragma unroll
                for (int half = 0; half < 2; half++) {
                    int rowl = wm + mf * 16 + g + half * 8;
                    float v0 = c1[mf][nf][half * 2 + 0] + bb0;
                    float v1 = c1[mf][nf][half * 2 + 1] + bb1;
                    v0 = 0.5f * v0 * (1.f + erff(v0 * 0.70710678118654752f));
                    v1 = 0.5f * v1 * (1.f + erff(v1 * 0.70710678118654752f));
                    *(bf162*)(hids + rowl * TS + coll) = __floats2bfloat162_rn(v0, v1);
                }
            }
        }
        __syncthreads();      // hids ready; wb0 free

        if (cch < 3) {
            #pragma unroll
            for (int r = 0; r < 8; r++) {
                int q = tid + r * 256;
                int row = q >> 4, ccc = q & 15;
                cp16(wb0 + row * TS + ccc * 8,
                     wfc1 + (long long)row * 512 + (cch + 1) * 128 + ccc * 8);
            }
        }
        asm volatile("cp.async.commit_group;\n");

        // -------- GEMM2: out += hid_c @ wfc2_c --------
        if (cch < 3) asm volatile("cp.async.wait_group 1;\n");
        else         asm volatile("cp.async.wait_group 0;\n");
        __syncthreads();

        #pragma unroll
        for (int ks = 0; ks < 8; ks++) {
            int kb = ks * 16;
            uint32_t a[4][4], b[4][2];
            #pragma unroll
            for (int mf = 0; mf < 4; mf++)
                ldm_x4(a[mf][0], a[mf][1], a[mf][2], a[mf][3],
                       hids + (wm + mf * 16 + t1 * 8 + rr) * TS + kb + t2 * 8);
            #pragma unroll
            for (int nh = 0; nh < 2; nh++) {
                uint32_t r0, r1, r2, r3;
                ldm_x4_t(r0, r1, r2, r3,
                         wb1 + (kb + t1 * 8 + rr) * TS + wn + nh * 16 + t2 * 8);
                b[nh * 2][0] = r0; b[nh * 2][1] = r1;
                b[nh * 2 + 1][0] = r2; b[nh * 2 + 1][1] = r3;
            }
            #pragma unroll
            for (int mf = 0; mf < 4; mf++)
                #pragma unroll
                for (int nf = 0; nf < 4; nf++)
                    mma_bf16(c2[mf][nf], a[mf], b[nf]);
        }
        __syncthreads();      // wb1 free

        if (cch < 3) {
            #pragma unroll
            for (int r = 0; r < 8; r++) {
                int q = tid + r * 256;
                int row = q >> 4, ccc = q & 15;
                cp16(wb1 + row * TS + ccc * 8,
                     wfc2 + (long long)((cch + 1) * 128 + row) * 128 + ccc * 8);
            }
            asm volatile("cp.async.commit_group;\n");
        }
    }

    // epilogue: out = c2 + bias2 + x1 residual (fp32)
    #pragma unroll
    for (int mf = 0; mf < 4; mf++) {
        #pragma unroll
        for (int nf = 0; nf < 4; nf++) {
            int col = wn + nf * 8 + tg * 2;
            float bb0 = b2[col], bb1 = b2[col + 1];
            #pragma unroll
            for (int half = 0; half < 2; half++) {
                int rowl = wm + mf * 16 + g + half * 8;
                float2 rv = *(const float2*)(x1f + rowl * 132 + col);
                float v0 = c2[mf][nf][half * 2 + 0] + bb0 + rv.x;
                float v1 = c2[mf][nf][half * 2 + 1] + bb1 + rv.y;
                *(float2*)(out + (long long)(m0 + rowl) * 128 + col) = make_float2(v0, v1);
            }
        }
    }
}

// ---------------------------------------------------------------------------
// launch
// ---------------------------------------------------------------------------
extern "C" void kernel_launch(void* const* d_in, const int* in_sizes, int n_in,
                              void* d_out, int out_size)
{
    const float* x       = (const float*)d_in[0];
    const float* norm1_g = (const float*)d_in[1];
    const float* norm1_b = (const float*)d_in[2];
    const float* qkv_w   = (const float*)d_in[3];
    const float* qkv_b   = (const float*)d_in[4];
    const float* rpb     = (const float*)d_in[5];
    const float* proj_w  = (const float*)d_in[6];
    const float* proj_b  = (const float*)d_in[7];
    const float* norm2_g = (const float*)d_in[8];
    const float* norm2_b = (const float*)d_in[9];
    const float* fc1_w   = (const float*)d_in[10];
    const float* fc1_b   = (const float*)d_in[11];
    const float* fc2_w   = (const float*)d_in[12];
    const float* fc2_b   = (const float*)d_in[13];
    float* out = (float*)d_out;

    bf16 *qkv, *att, *wqkv, *wproj, *wfc1, *wfc2;
    float *x1;
    cudaGetSymbolAddress((void**)&qkv,  g_qkv);
    cudaGetSymbolAddress((void**)&att,  g_att);
    cudaGetSymbolAddress((void**)&x1,   g_x1);
    cudaGetSymbolAddress((void**)&wqkv, g_wqkv);
    cudaGetSymbolAddress((void**)&wproj,g_wproj);
    cudaGetSymbolAddress((void**)&wfc1, g_wfc1);
    cudaGetSymbolAddress((void**)&wfc2, g_wfc2);

    cudaFuncSetAttribute(attn2_kernel, cudaFuncAttributeMaxDynamicSharedMemorySize, ATT2_SMEM);
    cudaFuncSetAttribute(gemm_k128<1,0,0,1>, cudaFuncAttributeMaxDynamicSharedMemorySize, K128_SMEM);
    cudaFuncSetAttribute(gemm_k128<0,0,1,0>, cudaFuncAttributeMaxDynamicSharedMemorySize, K128_SMEM);
    cudaFuncSetAttribute(mlp_kernel, cudaFuncAttributeMaxDynamicSharedMemorySize, MLP_SMEM);

    // 0) weight conversion
    f2bf_kernel<<<(128 * 384 + 255) / 256, 256>>>(qkv_w,  wqkv,  128 * 384);
    f2bf_kernel<<<(128 * 128 + 255) / 256, 256>>>(proj_w, wproj, 128 * 128);
    f2bf_kernel<<<(128 * 512 + 255) / 256, 256>>>(fc1_w,  wfc1,  128 * 512);
    f2bf_kernel<<<(512 * 128 + 255) / 256, 256>>>(fc2_w,  wfc2,  512 * 128);

    // 1) LN1 + gather + QKV projection -> bf16
    gemm_k128<1, 0, 0, 1><<<dim3(3, Bn_TOK / 128), 256, K128_SMEM>>>(
        x, wqkv, qkv_b, qkv, nullptr, norm1_g, norm1_b, 384);

    // 2) windowed attention -> bf16
    attn2_kernel<<<NWIN * 4, 256, ATT2_SMEM>>>(qkv, rpb, att);

    // 3) proj + window reverse + unshift + residual -> fp32 x1
    gemm_k128<0, 0, 1, 0><<<dim3(1, Bn_TOK / 128), 256, K128_SMEM>>>(
        att, wproj, proj_b, x1, x, nullptr, nullptr, 128);

    // 4) fused MLP: LN2 + fc1 + GELU + fc2 + residual -> fp32 out
    mlp_kernel<<<Bn_TOK / 128, 256, MLP_SMEM>>>(
        x1, wfc1, fc1_b, wfc2, fc2_b, norm2_g, norm2_b, out);
}